// round 1
// baseline (speedup 1.0000x reference)
#include <cuda_runtime.h>
#include <stdint.h>

// DisplaceChannel: out[b,c,y,x] = inp[b,c, y-off_y[p], x-off_x[p]] (p = c/32),
// zero where source index out of [0,64). Offsets are multiples of 32, so
// float4 (16B) vectors are uniformly valid/invalid and alignment is preserved.

#define BATCH 16
#define NPOS 9
#define CPP 32          // channels per position
#define CH (NPOS * CPP) // 288
#define H 64
#define W 64
#define W4 (W / 4)      // 16 float4 per row

__global__ __launch_bounds__(256)
void displace_kernel(const float4* __restrict__ in,
                     const int* __restrict__ offsets,
                     float4* __restrict__ out,
                     int total4)
{
    int idx = blockIdx.x * blockDim.x + threadIdx.x;
    if (idx >= total4) return;

    // Decompose: idx = ((b*CH + c)*H + y)*W4 + x4
    int x4 = idx & (W4 - 1);          // W4 = 16, power of 2
    int t  = idx >> 4;                // (b*CH + c)*H + y
    int y  = t & (H - 1);             // H = 64
    int bc = t >> 6;                  // b*CH + c
    int c  = bc % CH;
    int p  = c >> 5;                  // c / 32

    int off_x = __ldg(&offsets[2 * p]);
    int off_y = __ldg(&offsets[2 * p + 1]);

    int sy = y - off_y;
    int sx = (x4 << 2) - off_x;

    float4 v = make_float4(0.f, 0.f, 0.f, 0.f);
    if ((unsigned)sy < H && (unsigned)sx < W) {
        // source vector index: same bc, row sy, column sx/4
        v = __ldg(&in[(bc << 6 | sy) << 4 | (sx >> 2)]);
    }
    out[idx] = v;
}

extern "C" void kernel_launch(void* const* d_in, const int* in_sizes, int n_in,
                              void* d_out, int out_size)
{
    const float4* in = (const float4*)d_in[0];
    const int* offsets = (const int*)d_in[1];
    float4* out = (float4*)d_out;

    int total4 = out_size / 4;               // 16*288*64*64/4 = 4,718,592
    int threads = 256;
    int blocks = (total4 + threads - 1) / threads;
    displace_kernel<<<blocks, threads>>>(in, offsets, out, total4);
}

// round 2
// speedup vs baseline: 1.4168x; 1.4168x over previous
#include <cuda_runtime.h>
#include <stdint.h>

// DisplaceChannel: out[b,c,y,x] = inp[b,c, y-off_y[p], x-off_x[p]] (p = c/32),
// zero where source out of [0,64). Offsets are multiples of 32 -> float4
// vectors are uniformly valid/invalid and 16B alignment preserved.
//
// Layout: grid = (CH, B); one block owns one 64x64 plane (1024 float4).
// 256 threads x 4 vectors each, front-batched for MLP=4.

#define NPOS 9
#define CH 288          // 9 * 32
#define H 64
#define W 64
#define W4 16           // float4 per row
#define PLANE4 1024     // H * W4

__global__ __launch_bounds__(256)
void displace_kernel(const float4* __restrict__ in,
                     const int* __restrict__ offsets,
                     float4* __restrict__ out)
{
    const int c = blockIdx.x;          // 0..287
    const int b = blockIdx.y;          // 0..15
    const int p = c >> 5;              // position 0..8

    const int off_x = __ldg(&offsets[2 * p]);
    const int off_y = __ldg(&offsets[2 * p + 1]);

    const long base = ((long)b * CH + c) * PLANE4;
    const float4* __restrict__ src = in + base;
    float4* __restrict__ dst = out + base;

    const int t = threadIdx.x;

    // Each thread handles vectors t, t+256, t+512, t+768.
    float4 v[4];
    int didx[4];
#pragma unroll
    for (int j = 0; j < 4; j++) {
        const int vid = t + (j << 8);
        const int x4 = vid & (W4 - 1);
        const int y  = vid >> 4;
        const int sy = y - off_y;
        const int sx = (x4 << 2) - off_x;
        didx[j] = vid;
        v[j] = make_float4(0.f, 0.f, 0.f, 0.f);
        if ((unsigned)sy < H && (unsigned)sx < W) {
            v[j] = __ldg(&src[(sy << 4) + (sx >> 2)]);
        }
    }
#pragma unroll
    for (int j = 0; j < 4; j++) {
        __stcs(&dst[didx[j]], v[j]);   // streaming: output never re-read
    }
}

extern "C" void kernel_launch(void* const* d_in, const int* in_sizes, int n_in,
                              void* d_out, int out_size)
{
    const float4* in = (const float4*)d_in[0];
    const int* offsets = (const int*)d_in[1];
    float4* out = (float4*)d_out;

    dim3 grid(CH, 16);   // (channels, batch)
    displace_kernel<<<grid, 256>>>(in, offsets, out);
}